// round 5
// baseline (speedup 1.0000x reference)
#include <cuda_runtime.h>
#include <cuda_bf16.h>

// Problem constants (fixed by the dataset): B=512, S=2048, T=32
#define CRF_B 512
#define CRF_S 2048
#define CRF_T 32
#define GRID_BLOCKS 2048
#define BLOCK_THREADS 256
#define UNROLL 8

// ---------------------------------------------------------------------------
// init: zero the scalar output (d_out is poisoned to 0xAA before timing)
// ---------------------------------------------------------------------------
__global__ void crf_init_kernel(float* __restrict__ out) {
    if (threadIdx.x == 0) out[0] = 0.0f;
}

// ---------------------------------------------------------------------------
//   total = sum_{b,s,t} w[b,s] * em[b,s,t]              (w[b,0]=1, else mask)
//         + sum_b rowsum(trans)[tags[b,0]]
//         + T * sum_{b,s>=1} trans[tags[b,s-1], tags[b,s]] * mask[b,s]
//
// Phase 1 (cheap, irregular): per-row transition terms. 1M rows, 2 iters/thread.
// Phase 2 (hot, streaming):   branch-free unroll-8 float4 reduction over the
//                             128MB emissions tensor. Unconditional __ldcs
//                             (evict-first) loads -> MLP ~16/thread.
// ---------------------------------------------------------------------------
__global__ void __launch_bounds__(BLOCK_THREADS)
crf_main_kernel(const float* __restrict__ em,
                const int*   __restrict__ tags,
                const float* __restrict__ mask,
                const float* __restrict__ trans,
                float*       __restrict__ out) {
    __shared__ float trans_sh[CRF_T * CRF_T];
    __shared__ float rowsum_sh[CRF_T];

    for (int i = threadIdx.x; i < CRF_T * CRF_T; i += BLOCK_THREADS)
        trans_sh[i] = trans[i];
    __syncthreads();
    if (threadIdx.x < CRF_T) {
        float rs = 0.0f;
        #pragma unroll
        for (int t = 0; t < CRF_T; ++t) rs += trans_sh[threadIdx.x * CRF_T + t];
        rowsum_sh[threadIdx.x] = rs;
    }
    __syncthreads();

    const int tid      = blockIdx.x * BLOCK_THREADS + threadIdx.x;
    const int nthreads = GRID_BLOCKS * BLOCK_THREADS;   // 524288

    float acc = 0.0f;

    // ---- Phase 1: transition terms over rows r = b*S + s  (R = 1,048,576) ----
    const int R = CRF_B * CRF_S;
    for (int r = tid; r < R; r += nthreads) {
        const int s = r & (CRF_S - 1);
        if (s == 0) {
            acc += rowsum_sh[__ldg(&tags[r])];
        } else {
            const float m = __ldg(&mask[r]);
            if (m != 0.0f) {
                const int tp = __ldg(&tags[r - 1]);
                const int tc = __ldg(&tags[r]);
                acc += (float)CRF_T * m * trans_sh[tp * CRF_T + tc];
            }
        }
    }

    // ---- Phase 2: streaming masked-emission reduction ----
    const int N4 = R * (CRF_T / 4);                      // 8,388,608 float4s
    const float4* __restrict__ em4 = reinterpret_cast<const float4*>(em);

    int base = tid;
    // main unrolled body: all UNROLL loads independent -> front-batched LDGs
    for (; base + (UNROLL - 1) * nthreads < N4; base += UNROLL * nthreads) {
        float  w[UNROLL];
        float4 v[UNROLL];
        #pragma unroll
        for (int k = 0; k < UNROLL; ++k) {
            const int i = base + k * nthreads;
            const int r = i >> 3;
            const int s = r & (CRF_S - 1);
            w[k] = (s == 0) ? 1.0f : __ldg(&mask[r]);
            v[k] = __ldcs(&em4[i]);
        }
        #pragma unroll
        for (int k = 0; k < UNROLL; ++k)
            acc += w[k] * ((v[k].x + v[k].y) + (v[k].z + v[k].w));
    }
    // tail (empty for the exact 2048x256 launch, kept for safety)
    for (; base < N4; base += nthreads) {
        const int r = base >> 3;
        const int s = r & (CRF_S - 1);
        const float w = (s == 0) ? 1.0f : __ldg(&mask[r]);
        const float4 v = __ldcs(&em4[base]);
        acc += w * ((v.x + v.y) + (v.z + v.w));
    }

    // ---- block reduction: warp shuffle, then cross-warp via shared ----
    #pragma unroll
    for (int o = 16; o > 0; o >>= 1)
        acc += __shfl_down_sync(0xffffffffu, acc, o);

    __shared__ float warp_sums[BLOCK_THREADS / 32];
    const int lane = threadIdx.x & 31;
    const int wid  = threadIdx.x >> 5;
    if (lane == 0) warp_sums[wid] = acc;
    __syncthreads();

    if (wid == 0) {
        acc = (lane < (BLOCK_THREADS / 32)) ? warp_sums[lane] : 0.0f;
        #pragma unroll
        for (int o = 4; o > 0; o >>= 1)
            acc += __shfl_down_sync(0xffffffffu, acc, o);
        if (lane == 0) atomicAdd(out, acc);
    }
}

// ---------------------------------------------------------------------------
// kernel_launch — graph-capturable, allocation-free.
// Input order (metadata): emissions f32, tags i32, mask f32, transitions f32.
// Output: single f32 scalar.
// ---------------------------------------------------------------------------
extern "C" void kernel_launch(void* const* d_in, const int* in_sizes, int n_in,
                              void* d_out, int out_size) {
    (void)in_sizes; (void)n_in; (void)out_size;
    const float* em    = (const float*)d_in[0];
    const int*   tags  = (const int*)  d_in[1];
    const float* mask  = (const float*)d_in[2];
    const float* trans = (const float*)d_in[3];
    float* out = (float*)d_out;

    crf_init_kernel<<<1, 32>>>(out);
    crf_main_kernel<<<GRID_BLOCKS, BLOCK_THREADS>>>(em, tags, mask, trans, out);
}

// round 6
// speedup vs baseline: 1.0143x; 1.0143x over previous
#include <cuda_runtime.h>
#include <cuda_bf16.h>

// Problem constants (fixed by the dataset): B=512, S=2048, T=32
#define CRF_B 512
#define CRF_S 2048
#define CRF_T 32
#define GRID_BLOCKS 1184      // 148 SMs * 8 resident CTAs -> exactly one wave
#define BLOCK_THREADS 256
#define UNROLL 8

// ---------------------------------------------------------------------------
// init: zero the scalar output (d_out is poisoned to 0xAA before timing)
// ---------------------------------------------------------------------------
__global__ void crf_init_kernel(float* __restrict__ out) {
    if (threadIdx.x == 0) out[0] = 0.0f;
}

// ---------------------------------------------------------------------------
//   total = sum_{b,s,t} w[b,s] * em[b,s,t]              (w[b,0]=1, else mask)
//         + sum_b rowsum(trans)[tags[b,0]]
//         + T * sum_{b,s>=1} trans[tags[b,s-1], tags[b,s]] * mask[b,s]
//
// Phase 1: per-row transition terms (irregular, ~12MB of tags/mask).
// Phase 2: streaming unroll-8 float4 reduction over the 128MB emissions.
//          Loads are PREDICATED on w!=0: a fully-masked row (all 8 lanes
//          share w) never requests its 128B line -> ~10% DRAM saved.
// ---------------------------------------------------------------------------
__global__ void __launch_bounds__(BLOCK_THREADS)
crf_main_kernel(const float* __restrict__ em,
                const int*   __restrict__ tags,
                const float* __restrict__ mask,
                const float* __restrict__ trans,
                float*       __restrict__ out) {
    __shared__ float trans_sh[CRF_T * CRF_T];
    __shared__ float rowsum_sh[CRF_T];

    for (int i = threadIdx.x; i < CRF_T * CRF_T; i += BLOCK_THREADS)
        trans_sh[i] = trans[i];
    __syncthreads();
    if (threadIdx.x < CRF_T) {
        float rs = 0.0f;
        #pragma unroll
        for (int t = 0; t < CRF_T; ++t) rs += trans_sh[threadIdx.x * CRF_T + t];
        rowsum_sh[threadIdx.x] = rs;
    }
    __syncthreads();

    const int tid      = blockIdx.x * BLOCK_THREADS + threadIdx.x;
    const int nthreads = GRID_BLOCKS * BLOCK_THREADS;   // 303104

    float acc = 0.0f;

    // ---- Phase 1: transition terms over rows r = b*S + s  (R = 1,048,576) ----
    const int R = CRF_B * CRF_S;
    for (int r = tid; r < R; r += nthreads) {
        const int s = r & (CRF_S - 1);
        if (s == 0) {
            acc += rowsum_sh[__ldg(&tags[r])];
        } else {
            const float m = __ldg(&mask[r]);
            if (m != 0.0f) {
                const int tp = __ldg(&tags[r - 1]);
                const int tc = __ldg(&tags[r]);
                acc += (float)CRF_T * m * trans_sh[tp * CRF_T + tc];
            }
        }
    }

    // ---- Phase 2: streaming masked-emission reduction ----
    const int N4 = R * (CRF_T / 4);                      // 8,388,608 float4s
    const float4* __restrict__ em4 = reinterpret_cast<const float4*>(em);

    int base = tid;
    // main unrolled body: 8 independent predicated loads -> front-batched LDGs
    for (; base + (UNROLL - 1) * nthreads < N4; base += UNROLL * nthreads) {
        float  w[UNROLL];
        float4 v[UNROLL];
        #pragma unroll
        for (int k = 0; k < UNROLL; ++k) {
            const int i = base + k * nthreads;
            const int r = i >> 3;
            const int s = r & (CRF_S - 1);
            w[k] = (s == 0) ? 1.0f : __ldg(&mask[r]);
            v[k] = make_float4(0.f, 0.f, 0.f, 0.f);
            if (w[k] != 0.0f) v[k] = __ldcs(&em4[i]);   // predicated load
        }
        #pragma unroll
        for (int k = 0; k < UNROLL; ++k)
            acc += w[k] * ((v[k].x + v[k].y) + (v[k].z + v[k].w));
    }
    // tail: ~3-4 iterations per thread
    for (; base < N4; base += nthreads) {
        const int r = base >> 3;
        const int s = r & (CRF_S - 1);
        const float w = (s == 0) ? 1.0f : __ldg(&mask[r]);
        if (w != 0.0f) {
            const float4 v = __ldcs(&em4[base]);
            acc += w * ((v.x + v.y) + (v.z + v.w));
        }
    }

    // ---- block reduction: warp shuffle, then cross-warp via shared ----
    #pragma unroll
    for (int o = 16; o > 0; o >>= 1)
        acc += __shfl_down_sync(0xffffffffu, acc, o);

    __shared__ float warp_sums[BLOCK_THREADS / 32];
    const int lane = threadIdx.x & 31;
    const int wid  = threadIdx.x >> 5;
    if (lane == 0) warp_sums[wid] = acc;
    __syncthreads();

    if (wid == 0) {
        acc = (lane < (BLOCK_THREADS / 32)) ? warp_sums[lane] : 0.0f;
        #pragma unroll
        for (int o = 4; o > 0; o >>= 1)
            acc += __shfl_down_sync(0xffffffffu, acc, o);
        if (lane == 0) atomicAdd(out, acc);
    }
}

// ---------------------------------------------------------------------------
// kernel_launch — graph-capturable, allocation-free.
// Input order (metadata): emissions f32, tags i32, mask f32, transitions f32.
// Output: single f32 scalar.
// ---------------------------------------------------------------------------
extern "C" void kernel_launch(void* const* d_in, const int* in_sizes, int n_in,
                              void* d_out, int out_size) {
    (void)in_sizes; (void)n_in; (void)out_size;
    const float* em    = (const float*)d_in[0];
    const int*   tags  = (const int*)  d_in[1];
    const float* mask  = (const float*)d_in[2];
    const float* trans = (const float*)d_in[3];
    float* out = (float*)d_out;

    crf_init_kernel<<<1, 32>>>(out);
    crf_main_kernel<<<GRID_BLOCKS, BLOCK_THREADS>>>(em, tags, mask, trans, out);
}